// round 1
// baseline (speedup 1.0000x reference)
#include <cuda_runtime.h>
#include <math.h>

#define NMAX 8192
#define DIM 64
#define HID 32
#define TILE 128
#define KTOT 96                 // 64 (raw) + 32 (qmap features)
#define PITCH 132               // 128 + 4 pad to break smem bank conflicts
#define SMEM_BYTES ((2 * KTOT * PITCH + 2 * TILE) * sizeof(float))

// Scratch (allocation-free rule: __device__ globals)
__device__ float g_fa[NMAX * HID];
__device__ float g_fb[NMAX * HID];
__device__ float g_asq[NMAX];
__device__ float g_bsq[NMAX];

// ---------------------------------------------------------------------------
// Prologue: per-row feature map  feat = scale * (tanh(x@W1^T + b1) @ W2^T + b2)
// and squared norm. One warp per row; lane j owns hidden unit j.
// ---------------------------------------------------------------------------
__global__ void qmap_kernel(const float* __restrict__ x,
                            const float* __restrict__ W1,
                            const float* __restrict__ b1,
                            const float* __restrict__ W2,
                            const float* __restrict__ b2,
                            int n, int which, float featScale)
{
    __shared__ float sW1t[DIM * HID];   // [d][j] transposed -> conflict-free
    __shared__ float sW2t[HID * HID];   // [k][j] transposed
    __shared__ float sb1[HID], sb2[HID];

    int tid = threadIdx.x;
    for (int i = tid; i < HID * DIM; i += blockDim.x) {
        int j = i / DIM, d = i % DIM;
        sW1t[d * HID + j] = W1[i];
    }
    for (int i = tid; i < HID * HID; i += blockDim.x) {
        int j = i / HID, k = i % HID;
        sW2t[k * HID + j] = W2[i];
    }
    if (tid < HID) { sb1[tid] = b1[tid]; sb2[tid] = b2[tid]; }
    __syncthreads();

    float* feat = which ? g_fb : g_fa;
    float* sq   = which ? g_bsq : g_asq;

    int warp = tid >> 5, lane = tid & 31;
    int row = blockIdx.x * (blockDim.x >> 5) + warp;
    if (row >= n) return;

    float x0 = x[row * DIM + lane];
    float x1 = x[row * DIM + 32 + lane];

    // squared norm (warp reduce)
    float s = x0 * x0 + x1 * x1;
    #pragma unroll
    for (int o = 16; o; o >>= 1) s += __shfl_xor_sync(0xffffffffu, s, o);
    if (lane == 0) sq[row] = s;

    // layer 1: h = tanh(x @ W1^T + b1), lane owns unit `lane`
    float acc = sb1[lane];
    #pragma unroll
    for (int d = 0; d < 32; d++) {
        float xv = __shfl_sync(0xffffffffu, x0, d);
        acc = fmaf(xv, sW1t[d * HID + lane], acc);
    }
    #pragma unroll
    for (int d = 0; d < 32; d++) {
        float xv = __shfl_sync(0xffffffffu, x1, d);
        acc = fmaf(xv, sW1t[(32 + d) * HID + lane], acc);
    }
    float h = tanhf(acc);

    // layer 2
    float acc2 = sb2[lane];
    #pragma unroll
    for (int k = 0; k < 32; k++) {
        float hv = __shfl_sync(0xffffffffu, h, k);
        acc2 = fmaf(hv, sW2t[k * HID + lane], acc2);
    }
    feat[row * HID + lane] = featScale * acc2;
}

// ---------------------------------------------------------------------------
// Main Gram kernel: out = 0.5 * (fa@fb^T) + 0.5 * exp(-max(asq+bsq-2 a@b^T, 0))
// (0.5 for the q-term is pre-folded into fa.)
// 128x128 tile per CTA, 256 threads, 8x8 per thread. K=96 loaded once.
// ---------------------------------------------------------------------------
__global__ __launch_bounds__(256, 2)
void gram_kernel(const float* __restrict__ a, const float* __restrict__ b,
                 float* __restrict__ out, int M)
{
    extern __shared__ float smem[];
    float* Af    = smem;                     // [KTOT][PITCH]  k-major
    float* Bf    = Af + KTOT * PITCH;
    float* s_asq = Bf + KTOT * PITCH;        // [128]
    float* s_bsq = s_asq + TILE;             // [128]

    const int tid = threadIdx.x;
    const int tx = tid & 15, ty = tid >> 4;
    const int rowBase = blockIdx.y * TILE;
    const int colBase = blockIdx.x * TILE;

    // ---- load raw 128x64 tiles, transposed to k-major ----
    const float4* a4 = (const float4*)(a + (size_t)rowBase * DIM);
    const float4* b4 = (const float4*)(b + (size_t)colBase * DIM);
    #pragma unroll
    for (int it = 0; it < 8; it++) {
        int lin = tid + it * 256;          // 0..2047
        int r = lin >> 4;                  // row in tile
        int c4 = lin & 15;                 // float4 column
        float4 v = a4[r * 16 + c4];
        Af[(c4 * 4 + 0) * PITCH + r] = v.x;
        Af[(c4 * 4 + 1) * PITCH + r] = v.y;
        Af[(c4 * 4 + 2) * PITCH + r] = v.z;
        Af[(c4 * 4 + 3) * PITCH + r] = v.w;
        float4 w = b4[r * 16 + c4];
        Bf[(c4 * 4 + 0) * PITCH + r] = w.x;
        Bf[(c4 * 4 + 1) * PITCH + r] = w.y;
        Bf[(c4 * 4 + 2) * PITCH + r] = w.z;
        Bf[(c4 * 4 + 3) * PITCH + r] = w.w;
    }
    // ---- load 128x32 feature tiles, transposed, at k=64..95 ----
    const float4* fa4 = (const float4*)(g_fa + (size_t)rowBase * HID);
    const float4* fb4 = (const float4*)(g_fb + (size_t)colBase * HID);
    #pragma unroll
    for (int it = 0; it < 4; it++) {
        int lin = tid + it * 256;          // 0..1023
        int r = lin >> 3;
        int c4 = lin & 7;
        float4 v = fa4[r * 8 + c4];
        Af[(64 + c4 * 4 + 0) * PITCH + r] = v.x;
        Af[(64 + c4 * 4 + 1) * PITCH + r] = v.y;
        Af[(64 + c4 * 4 + 2) * PITCH + r] = v.z;
        Af[(64 + c4 * 4 + 3) * PITCH + r] = v.w;
        float4 w = fb4[r * 8 + c4];
        Bf[(64 + c4 * 4 + 0) * PITCH + r] = w.x;
        Bf[(64 + c4 * 4 + 1) * PITCH + r] = w.y;
        Bf[(64 + c4 * 4 + 2) * PITCH + r] = w.z;
        Bf[(64 + c4 * 4 + 3) * PITCH + r] = w.w;
    }
    if (tid < TILE)           s_asq[tid]        = g_asq[rowBase + tid];
    else if (tid < 2 * TILE)  s_bsq[tid - TILE] = g_bsq[colBase + tid - TILE];
    __syncthreads();

    float acc[8][8];
    #pragma unroll
    for (int i = 0; i < 8; i++)
        #pragma unroll
        for (int j = 0; j < 8; j++) acc[i][j] = 0.0f;

    // ---- phase 1: acc = a . b over k=0..63 ----
    #pragma unroll 4
    for (int k = 0; k < 64; k++) {
        float ar[8], br[8];
        const float4* pa = (const float4*)&Af[k * PITCH + ty * 8];
        const float4* pb = (const float4*)&Bf[k * PITCH + tx * 8];
        float4 a0 = pa[0], a1 = pa[1];
        float4 b0 = pb[0], b1 = pb[1];
        ar[0]=a0.x; ar[1]=a0.y; ar[2]=a0.z; ar[3]=a0.w;
        ar[4]=a1.x; ar[5]=a1.y; ar[6]=a1.z; ar[7]=a1.w;
        br[0]=b0.x; br[1]=b0.y; br[2]=b0.z; br[3]=b0.w;
        br[4]=b1.x; br[5]=b1.y; br[6]=b1.z; br[7]=b1.w;
        #pragma unroll
        for (int i = 0; i < 8; i++)
            #pragma unroll
            for (int j = 0; j < 8; j++)
                acc[i][j] = fmaf(ar[i], br[j], acc[i][j]);
    }

    // ---- RBF transform: acc = 0.5 * exp(-max(asq+bsq-2*acc, 0)) ----
    {
        float sa[8], sb[8];
        #pragma unroll
        for (int i = 0; i < 8; i++) sa[i] = s_asq[ty * 8 + i];
        #pragma unroll
        for (int j = 0; j < 8; j++) sb[j] = s_bsq[tx * 8 + j];
        #pragma unroll
        for (int i = 0; i < 8; i++)
            #pragma unroll
            for (int j = 0; j < 8; j++) {
                float d = fmaxf(sa[i] + sb[j] - 2.0f * acc[i][j], 0.0f);
                acc[i][j] = 0.5f * __expf(-d);
            }
    }

    // ---- phase 2: acc += fa . fb over k=64..95 (0.5 pre-folded into fa) ----
    #pragma unroll 4
    for (int k = 64; k < 96; k++) {
        float ar[8], br[8];
        const float4* pa = (const float4*)&Af[k * PITCH + ty * 8];
        const float4* pb = (const float4*)&Bf[k * PITCH + tx * 8];
        float4 a0 = pa[0], a1 = pa[1];
        float4 b0 = pb[0], b1 = pb[1];
        ar[0]=a0.x; ar[1]=a0.y; ar[2]=a0.z; ar[3]=a0.w;
        ar[4]=a1.x; ar[5]=a1.y; ar[6]=a1.z; ar[7]=a1.w;
        br[0]=b0.x; br[1]=b0.y; br[2]=b0.z; br[3]=b0.w;
        br[4]=b1.x; br[5]=b1.y; br[6]=b1.z; br[7]=b1.w;
        #pragma unroll
        for (int i = 0; i < 8; i++)
            #pragma unroll
            for (int j = 0; j < 8; j++)
                acc[i][j] = fmaf(ar[i], br[j], acc[i][j]);
    }

    // ---- store 8x8 block, vectorized ----
    #pragma unroll
    for (int i = 0; i < 8; i++) {
        size_t r = (size_t)(rowBase + ty * 8 + i);
        float4* o4 = (float4*)(out + r * (size_t)M + colBase + tx * 8);
        o4[0] = make_float4(acc[i][0], acc[i][1], acc[i][2], acc[i][3]);
        o4[1] = make_float4(acc[i][4], acc[i][5], acc[i][6], acc[i][7]);
    }
}

extern "C" void kernel_launch(void* const* d_in, const int* in_sizes, int n_in,
                              void* d_out, int out_size)
{
    const float* a  = (const float*)d_in[0];
    const float* b  = (const float*)d_in[1];
    const float* W1 = (const float*)d_in[2];
    const float* b1 = (const float*)d_in[3];
    const float* W2 = (const float*)d_in[4];
    const float* b2 = (const float*)d_in[5];
    float* out = (float*)d_out;

    const int N = in_sizes[0] / DIM;   // 8192
    const int M = in_sizes[1] / DIM;   // 8192

    // Prologue: features + row norms (0.5 quantum weight folded into fa)
    qmap_kernel<<<(N + 7) / 8, 256>>>(a, W1, b1, W2, b2, N, 0, 0.5f);
    qmap_kernel<<<(M + 7) / 8, 256>>>(b, W1, b1, W2, b2, M, 1, 1.0f);

    // Main Gram kernel
    cudaFuncSetAttribute(gram_kernel,
                         cudaFuncAttributeMaxDynamicSharedMemorySize,
                         (int)SMEM_BYTES);
    dim3 grid(M / TILE, N / TILE);
    gram_kernel<<<grid, 256, SMEM_BYTES>>>(a, b, out, M);
}

// round 2
// speedup vs baseline: 1.0341x; 1.0341x over previous
#include <cuda_runtime.h>
#include <math.h>
#include <stdint.h>

#define NMAX 8192
#define DIM 64
#define HID 32
#define TILE 128
#define KTOT 96                 // 64 (raw) + 32 (qmap features)
#define PITCH 132               // 128 + 4 pad to break smem bank conflicts
#define SMEM_BYTES ((2 * KTOT * PITCH + 2 * TILE) * sizeof(float))

// Scratch (allocation-free rule: __device__ globals)
__device__ float g_fa[NMAX * HID];
__device__ float g_fb[NMAX * HID];
__device__ float g_asq[NMAX];
__device__ float g_bsq[NMAX];

// Packed f32x2 ops (Blackwell sm_103a) — the only route to 128 FP32 FLOP/cyc/SM
#define FMA_F32X2(d, a, b, c) \
    asm("fma.rn.f32x2 %0, %1, %2, %3;" : "=l"(d) : "l"(a), "l"(b), "l"(c))
#define PACK_F32X2(out, lo, hi) \
    asm("mov.b64 %0, {%1, %2};" : "=l"(out) : "f"(lo), "f"(hi))
#define UNPACK_F32X2(lo, hi, in) \
    asm("mov.b64 {%0, %1}, %2;" : "=f"(lo), "=f"(hi) : "l"(in))

// ---------------------------------------------------------------------------
// Prologue: one THREAD per row. Weights in smem (warp-uniform broadcast reads).
// feat = scale * (tanh(x@W1^T + b1) @ W2^T + b2), plus squared row norm.
// Handles both a (blockIdx.y==0) and b (blockIdx.y==1) in one launch.
// ---------------------------------------------------------------------------
__global__ void qmap_kernel(const float* __restrict__ a,
                            const float* __restrict__ bmat,
                            const float* __restrict__ W1,
                            const float* __restrict__ b1,
                            const float* __restrict__ W2,
                            const float* __restrict__ b2)
{
    __shared__ float sW1t[DIM][HID];   // [d][j]
    __shared__ float sW2t[HID][HID];   // [k][j]
    __shared__ float sb1[HID], sb2[HID];

    const int tid = threadIdx.x;
    for (int i = tid; i < HID * DIM; i += blockDim.x) {
        int j = i / DIM, d = i % DIM;
        sW1t[d][j] = W1[i];
    }
    for (int i = tid; i < HID * HID; i += blockDim.x) {
        int j = i / HID, k = i % HID;
        sW2t[k][j] = W2[i];
    }
    if (tid < HID) { sb1[tid] = b1[tid]; sb2[tid] = b2[tid]; }
    __syncthreads();

    const int which = blockIdx.y;
    const float* __restrict__ x = which ? bmat : a;
    float* feat = which ? g_fb : g_fa;
    float* sq   = which ? g_bsq : g_asq;
    const float scale = which ? 1.0f : 0.5f;   // fold quantum weight into fa

    const int row = blockIdx.x * blockDim.x + tid;

    float h[HID];
    #pragma unroll
    for (int j = 0; j < HID; j++) h[j] = sb1[j];

    float s = 0.0f;
    const float4* xr = (const float4*)(x + (size_t)row * DIM);
    #pragma unroll
    for (int d4 = 0; d4 < DIM / 4; d4++) {
        float4 v = xr[d4];
        s += v.x * v.x + v.y * v.y + v.z * v.z + v.w * v.w;
        #pragma unroll
        for (int j = 0; j < HID; j++) {
            h[j] = fmaf(v.x, sW1t[4 * d4 + 0][j], h[j]);
            h[j] = fmaf(v.y, sW1t[4 * d4 + 1][j], h[j]);
            h[j] = fmaf(v.z, sW1t[4 * d4 + 2][j], h[j]);
            h[j] = fmaf(v.w, sW1t[4 * d4 + 3][j], h[j]);
        }
    }
    sq[row] = s;

    #pragma unroll
    for (int j = 0; j < HID; j++) h[j] = tanhf(h[j]);

    float o[HID];
    #pragma unroll
    for (int j = 0; j < HID; j++) o[j] = sb2[j];
    #pragma unroll
    for (int k = 0; k < HID; k++)
        #pragma unroll
        for (int j = 0; j < HID; j++)
            o[j] = fmaf(h[k], sW2t[k][j], o[j]);

    float4* fo = (float4*)(feat + (size_t)row * HID);
    #pragma unroll
    for (int q = 0; q < HID / 4; q++)
        fo[q] = make_float4(scale * o[4 * q + 0], scale * o[4 * q + 1],
                            scale * o[4 * q + 2], scale * o[4 * q + 3]);
}

// ---------------------------------------------------------------------------
// Main Gram kernel: out = 0.5 * (fa@fb^T) + 0.5 * exp(-max(asq+bsq-2 a@b^T, 0))
// 128x128 tile / CTA, 256 threads, 8x8 per thread with f32x2-packed
// accumulators (row pairs). K=96 loaded once into smem (no K mainloop).
// ---------------------------------------------------------------------------
__global__ __launch_bounds__(256, 2)
void gram_kernel(const float* __restrict__ a, const float* __restrict__ b,
                 float* __restrict__ out, int M)
{
    extern __shared__ float smem[];
    float* Af    = smem;                     // [KTOT][PITCH]  k-major
    float* Bf    = Af + KTOT * PITCH;
    float* s_asq = Bf + KTOT * PITCH;        // [128]
    float* s_bsq = s_asq + TILE;             // [128]

    const int tid = threadIdx.x;
    const int tx = tid & 15, ty = tid >> 4;
    const int rowBase = blockIdx.y * TILE;
    const int colBase = blockIdx.x * TILE;

    // ---- load raw 128x64 tiles, transposed to k-major ----
    const float4* a4 = (const float4*)(a + (size_t)rowBase * DIM);
    const float4* b4 = (const float4*)(b + (size_t)colBase * DIM);
    #pragma unroll
    for (int it = 0; it < 8; it++) {
        int lin = tid + it * 256;          // 0..2047
        int r = lin >> 4;                  // row in tile
        int c4 = lin & 15;                 // float4 column
        float4 v = a4[r * 16 + c4];
        Af[(c4 * 4 + 0) * PITCH + r] = v.x;
        Af[(c4 * 4 + 1) * PITCH + r] = v.y;
        Af[(c4 * 4 + 2) * PITCH + r] = v.z;
        Af[(c4 * 4 + 3) * PITCH + r] = v.w;
        float4 w = b4[r * 16 + c4];
        Bf[(c4 * 4 + 0) * PITCH + r] = w.x;
        Bf[(c4 * 4 + 1) * PITCH + r] = w.y;
        Bf[(c4 * 4 + 2) * PITCH + r] = w.z;
        Bf[(c4 * 4 + 3) * PITCH + r] = w.w;
    }
    // ---- load 128x32 feature tiles, transposed, at k=64..95 ----
    const float4* fa4 = (const float4*)(g_fa + (size_t)rowBase * HID);
    const float4* fb4 = (const float4*)(g_fb + (size_t)colBase * HID);
    #pragma unroll
    for (int it = 0; it < 4; it++) {
        int lin = tid + it * 256;          // 0..1023
        int r = lin >> 3;
        int c4 = lin & 7;
        float4 v = fa4[r * 8 + c4];
        Af[(64 + c4 * 4 + 0) * PITCH + r] = v.x;
        Af[(64 + c4 * 4 + 1) * PITCH + r] = v.y;
        Af[(64 + c4 * 4 + 2) * PITCH + r] = v.z;
        Af[(64 + c4 * 4 + 3) * PITCH + r] = v.w;
        float4 w = fb4[r * 8 + c4];
        Bf[(64 + c4 * 4 + 0) * PITCH + r] = w.x;
        Bf[(64 + c4 * 4 + 1) * PITCH + r] = w.y;
        Bf[(64 + c4 * 4 + 2) * PITCH + r] = w.z;
        Bf[(64 + c4 * 4 + 3) * PITCH + r] = w.w;
    }
    if (tid < TILE)           s_asq[tid]        = g_asq[rowBase + tid];
    else if (tid < 2 * TILE)  s_bsq[tid - TILE] = g_bsq[colBase + tid - TILE];
    __syncthreads();

    // acc[ip][j] packs output rows (2*ip, 2*ip+1) for column j
    uint64_t acc[4][8];
    #pragma unroll
    for (int ip = 0; ip < 4; ip++)
        #pragma unroll
        for (int j = 0; j < 8; j++) acc[ip][j] = 0ull;

    // ---- phase 1: acc = a . b over k=0..63 (packed f32x2 FMA) ----
    #pragma unroll 2
    for (int k = 0; k < 64; k++) {
        const uint64_t* pa = (const uint64_t*)&Af[k * PITCH + ty * 8];
        uint64_t ap0 = pa[0], ap1 = pa[1], ap2 = pa[2], ap3 = pa[3];
        const float4* pb = (const float4*)&Bf[k * PITCH + tx * 8];
        float4 b0 = pb[0], b1 = pb[1];
        uint64_t bd[8];
        PACK_F32X2(bd[0], b0.x, b0.x); PACK_F32X2(bd[1], b0.y, b0.y);
        PACK_F32X2(bd[2], b0.z, b0.z); PACK_F32X2(bd[3], b0.w, b0.w);
        PACK_F32X2(bd[4], b1.x, b1.x); PACK_F32X2(bd[5], b1.y, b1.y);
        PACK_F32X2(bd[6], b1.z, b1.z); PACK_F32X2(bd[7], b1.w, b1.w);
        #pragma unroll
        for (int j = 0; j < 8; j++) {
            FMA_F32X2(acc[0][j], ap0, bd[j], acc[0][j]);
            FMA_F32X2(acc[1][j], ap1, bd[j], acc[1][j]);
            FMA_F32X2(acc[2][j], ap2, bd[j], acc[2][j]);
            FMA_F32X2(acc[3][j], ap3, bd[j], acc[3][j]);
        }
    }

    // ---- RBF transform: acc = 0.5 * exp(-max(asq+bsq-2*acc, 0)) ----
    {
        float sa[8], sb[8];
        #pragma unroll
        for (int i = 0; i < 8; i++) sa[i] = s_asq[ty * 8 + i];
        #pragma unroll
        for (int j = 0; j < 8; j++) sb[j] = s_bsq[tx * 8 + j];
        #pragma unroll
        for (int ip = 0; ip < 4; ip++)
            #pragma unroll
            for (int j = 0; j < 8; j++) {
                float lo, hi;
                UNPACK_F32X2(lo, hi, acc[ip][j]);
                float d0 = fmaxf(sa[2 * ip + 0] + sb[j] - 2.0f * lo, 0.0f);
                float d1 = fmaxf(sa[2 * ip + 1] + sb[j] - 2.0f * hi, 0.0f);
                lo = 0.5f * __expf(-d0);
                hi = 0.5f * __expf(-d1);
                PACK_F32X2(acc[ip][j], lo, hi);
            }
    }

    // ---- phase 2: acc += fa . fb over k=64..95 (0.5 pre-folded into fa) ----
    #pragma unroll 2
    for (int k = 64; k < 96; k++) {
        const uint64_t* pa = (const uint64_t*)&Af[k * PITCH + ty * 8];
        uint64_t ap0 = pa[0], ap1 = pa[1], ap2 = pa[2], ap3 = pa[3];
        const float4* pb = (const float4*)&Bf[k * PITCH + tx * 8];
        float4 b0 = pb[0], b1 = pb[1];
        uint64_t bd[8];
        PACK_F32X2(bd[0], b0.x, b0.x); PACK_F32X2(bd[1], b0.y, b0.y);
        PACK_F32X2(bd[2], b0.z, b0.z); PACK_F32X2(bd[3], b0.w, b0.w);
        PACK_F32X2(bd[4], b1.x, b1.x); PACK_F32X2(bd[5], b1.y, b1.y);
        PACK_F32X2(bd[6], b1.z, b1.z); PACK_F32X2(bd[7], b1.w, b1.w);
        #pragma unroll
        for (int j = 0; j < 8; j++) {
            FMA_F32X2(acc[0][j], ap0, bd[j], acc[0][j]);
            FMA_F32X2(acc[1][j], ap1, bd[j], acc[1][j]);
            FMA_F32X2(acc[2][j], ap2, bd[j], acc[2][j]);
            FMA_F32X2(acc[3][j], ap3, bd[j], acc[3][j]);
        }
    }

    // ---- store 8x8 block, vectorized ----
    #pragma unroll
    for (int ip = 0; ip < 4; ip++) {
        float r0[8], r1[8];
        #pragma unroll
        for (int j = 0; j < 8; j++) UNPACK_F32X2(r0[j], r1[j], acc[ip][j]);
        size_t ra = (size_t)(rowBase + ty * 8 + 2 * ip);
        float4* o0 = (float4*)(out + ra * (size_t)M + colBase + tx * 8);
        float4* o1 = (float4*)(out + (ra + 1) * (size_t)M + colBase + tx * 8);
        o0[0] = make_float4(r0[0], r0[1], r0[2], r0[3]);
        o0[1] = make_float4(r0[4], r0[5], r0[6], r0[7]);
        o1[0] = make_float4(r1[0], r1[1], r1[2], r1[3]);
        o1[1] = make_float4(r1[4], r1[5], r1[6], r1[7]);
    }
}

extern "C" void kernel_launch(void* const* d_in, const int* in_sizes, int n_in,
                              void* d_out, int out_size)
{
    const float* a  = (const float*)d_in[0];
    const float* b  = (const float*)d_in[1];
    const float* W1 = (const float*)d_in[2];
    const float* b1 = (const float*)d_in[3];
    const float* W2 = (const float*)d_in[4];
    const float* b2 = (const float*)d_in[5];
    float* out = (float*)d_out;

    const int N = in_sizes[0] / DIM;   // 8192
    const int M = in_sizes[1] / DIM;   // 8192

    // Prologue: features + row norms, both inputs in one launch
    dim3 qgrid(N / 256, 2);
    qmap_kernel<<<qgrid, 256>>>(a, b, W1, b1, W2, b2);

    // Main Gram kernel
    cudaFuncSetAttribute(gram_kernel,
                         cudaFuncAttributeMaxDynamicSharedMemorySize,
                         (int)SMEM_BYTES);
    dim3 grid(M / TILE, N / TILE);
    gram_kernel<<<grid, 256, SMEM_BYTES>>>(a, b, out, M);
}

// round 4
// speedup vs baseline: 2.0431x; 1.9757x over previous
#include <cuda_runtime.h>
#include <cuda_bf16.h>
#include <math.h>
#include <stdint.h>

#define DIM 64
#define HID 32
#define NMAX 8192
#define KTOT 96                      // 64 raw + 32 features

// ---------------------------------------------------------------------------
// Device-global scratch (allocation-free rule).
// Hi/lo bf16 split images, row-major [N][96]: k 0..63 raw, 64..95 features.
// ---------------------------------------------------------------------------
__device__ __nv_bfloat16 g_Ah[NMAX * KTOT];
__device__ __nv_bfloat16 g_Al[NMAX * KTOT];
__device__ __nv_bfloat16 g_Bh[NMAX * KTOT];
__device__ __nv_bfloat16 g_Bl[NMAX * KTOT];
__device__ float g_asq[NMAX];
__device__ float g_bsq[NMAX];

// ============================ PTX helpers (baseline ISA only) ==============
__device__ __forceinline__ uint32_t smem_u32(const void* p) {
    uint32_t a;
    asm("{ .reg .u64 t; cvta.to.shared.u64 t, %1; cvt.u32.u64 %0, t; }"
        : "=r"(a) : "l"(p));
    return a;
}

__device__ __forceinline__ void ldsm_x4(uint32_t* r, uint32_t addr) {
    asm volatile("ldmatrix.sync.aligned.m8n8.x4.shared.b16 {%0,%1,%2,%3}, [%4];"
                 : "=r"(r[0]), "=r"(r[1]), "=r"(r[2]), "=r"(r[3]) : "r"(addr));
}
__device__ __forceinline__ void ldsm_x2(uint32_t* r, uint32_t addr) {
    asm volatile("ldmatrix.sync.aligned.m8n8.x2.shared.b16 {%0,%1}, [%2];"
                 : "=r"(r[0]), "=r"(r[1]) : "r"(addr));
}
__device__ __forceinline__ void mma16816(float* d, const uint32_t* a,
                                         const uint32_t* b) {
    asm volatile(
        "mma.sync.aligned.m16n8k16.row.col.f32.bf16.bf16.f32 "
        "{%0,%1,%2,%3}, {%4,%5,%6,%7}, {%8,%9}, {%0,%1,%2,%3};"
        : "+f"(d[0]), "+f"(d[1]), "+f"(d[2]), "+f"(d[3])
        : "r"(a[0]), "r"(a[1]), "r"(a[2]), "r"(a[3]), "r"(b[0]), "r"(b[1]));
}

// ---------------------------------------------------------------------------
// Prologue: one thread per row. asq/bsq + qmap features + hi/lo bf16 split.
// ---------------------------------------------------------------------------
__device__ __forceinline__ void split8(const float* v, uint4& h4, uint4& l4) {
    uint32_t hs[8], ls[8];
    #pragma unroll
    for (int i = 0; i < 8; i++) {
        __nv_bfloat16 h = __float2bfloat16(v[i]);
        float r = v[i] - __bfloat162float(h);
        __nv_bfloat16 l = __float2bfloat16(r);
        hs[i] = (uint32_t)__bfloat16_as_ushort(h);
        ls[i] = (uint32_t)__bfloat16_as_ushort(l);
    }
    h4.x = hs[0] | (hs[1] << 16); h4.y = hs[2] | (hs[3] << 16);
    h4.z = hs[4] | (hs[5] << 16); h4.w = hs[6] | (hs[7] << 16);
    l4.x = ls[0] | (ls[1] << 16); l4.y = ls[2] | (ls[3] << 16);
    l4.z = ls[4] | (ls[5] << 16); l4.w = ls[6] | (ls[7] << 16);
}

__global__ void prologue_kernel(const float* __restrict__ a,
                                const float* __restrict__ bmat,
                                const float* __restrict__ W1,
                                const float* __restrict__ b1,
                                const float* __restrict__ W2,
                                const float* __restrict__ b2)
{
    __shared__ float sW1t[DIM][HID];
    __shared__ float sW2t[HID][HID];
    __shared__ float sb1[HID], sb2[HID];

    const int tid = threadIdx.x;
    for (int i = tid; i < HID * DIM; i += blockDim.x) {
        int j = i / DIM, d = i % DIM;
        sW1t[d][j] = W1[i];
    }
    for (int i = tid; i < HID * HID; i += blockDim.x) {
        int j = i / HID, k = i % HID;
        sW2t[k][j] = W2[i];
    }
    if (tid < HID) { sb1[tid] = b1[tid]; sb2[tid] = b2[tid]; }
    __syncthreads();

    const int side = blockIdx.y;
    const float* __restrict__ x = side ? bmat : a;
    const float scale = side ? 1.0f : 0.5f;   // fold quantum weight into fa
    const int row = blockIdx.x * blockDim.x + tid;

    float v[DIM];
    const float4* xr = (const float4*)(x + (size_t)row * DIM);
    #pragma unroll
    for (int q = 0; q < DIM / 4; q++) {
        float4 t = xr[q];
        v[4 * q + 0] = t.x; v[4 * q + 1] = t.y;
        v[4 * q + 2] = t.z; v[4 * q + 3] = t.w;
    }

    float s = 0.0f;
    #pragma unroll
    for (int d = 0; d < DIM; d++) s = fmaf(v[d], v[d], s);
    if (side) g_bsq[row] = s; else g_asq[row] = s;

    float h[HID];
    #pragma unroll
    for (int j = 0; j < HID; j++) h[j] = sb1[j];
    #pragma unroll
    for (int d = 0; d < DIM; d++)
        #pragma unroll
        for (int j = 0; j < HID; j++)
            h[j] = fmaf(v[d], sW1t[d][j], h[j]);
    #pragma unroll
    for (int j = 0; j < HID; j++) h[j] = tanhf(h[j]);

    float o[HID];
    #pragma unroll
    for (int j = 0; j < HID; j++) o[j] = sb2[j];
    #pragma unroll
    for (int k = 0; k < HID; k++)
        #pragma unroll
        for (int j = 0; j < HID; j++)
            o[j] = fmaf(h[k], sW2t[k][j], o[j]);
    #pragma unroll
    for (int j = 0; j < HID; j++) o[j] *= scale;

    uint4* dh = (uint4*)((side ? g_Bh : g_Ah) + (size_t)row * KTOT);
    uint4* dl = (uint4*)((side ? g_Bl : g_Al) + (size_t)row * KTOT);
    #pragma unroll
    for (int c = 0; c < 8; c++) {            // raw, k 0..63
        uint4 h4, l4;
        split8(&v[c * 8], h4, l4);
        dh[c] = h4; dl[c] = l4;
    }
    #pragma unroll
    for (int c = 0; c < 4; c++) {            // features, k 64..95
        uint4 h4, l4;
        split8(&o[c * 8], h4, l4);
        dh[8 + c] = h4; dl[8 + c] = l4;
    }
}

// ---------------------------------------------------------------------------
// Main Gram kernel: 128x128 tile, 8 warps (2x4), warp tile 64x32.
// bf16 HMMA 3-pass emulated fp32. K=96 in 6 k16-steps; RBF transform after
// step 3 (raw k done), then 2 feature steps accumulate on top.
// ---------------------------------------------------------------------------
#define LDB 208                      // smem row stride bytes (104 bf16)
#define IMG_BYTES (128 * LDB)        // 26624
#define OFF_AH 0
#define OFF_AL IMG_BYTES
#define OFF_BH (2 * IMG_BYTES)
#define OFF_BL (3 * IMG_BYTES)
#define OFF_ASQ (4 * IMG_BYTES)
#define OFF_BSQ (OFF_ASQ + 512)
#define SMEM_DYN (OFF_BSQ + 512)

__global__ __launch_bounds__(256, 1)
void gram_mma_kernel(float* __restrict__ out, int M)
{
    extern __shared__ char smem[];
    const uint32_t sb = smem_u32(smem);
    const int tid = threadIdx.x;
    const int wid = tid >> 5, lane = tid & 31;
    const int rowBase = blockIdx.y * 128, colBase = blockIdx.x * 128;

    // ---- load 4 images global -> smem (stride 96 -> 104 bf16) ----
    {
        const uint4* gsrc[4] = {
            (const uint4*)(g_Ah + (size_t)rowBase * KTOT),
            (const uint4*)(g_Al + (size_t)rowBase * KTOT),
            (const uint4*)(g_Bh + (size_t)colBase * KTOT),
            (const uint4*)(g_Bl + (size_t)colBase * KTOT) };
        uint4* sdst = (uint4*)smem;
        #pragma unroll
        for (int img = 0; img < 4; img++) {
            #pragma unroll
            for (int i = 0; i < 6; i++) {
                int lin = tid + i * 256;             // 0..1535
                int r = lin / 12, c = lin % 12;
                sdst[img * (IMG_BYTES / 16) + r * 13 + c] = gsrc[img][lin];
            }
        }
        float* s_asq = (float*)(smem + OFF_ASQ);
        float* s_bsq = (float*)(smem + OFF_BSQ);
        if (tid < 128) s_asq[tid] = g_asq[rowBase + tid];
        else           s_bsq[tid - 128] = g_bsq[colBase + tid - 128];
    }
    __syncthreads();

    const int wm = wid >> 2, wn = wid & 3;   // warp grid 2 x 4
    const int g = lane >> 2, t = lane & 3;

    // ldmatrix lane addresses
    const uint32_t aAddr = sb + OFF_AH +
        (wm * 64 + (lane & 15)) * LDB + (lane >> 4) * 16;
    const uint32_t bAddr = sb + OFF_BH +
        (wn * 32 + (lane & 7)) * LDB + ((lane >> 3) & 1) * 16;

    float acc[4][4][4];
    #pragma unroll
    for (int mi = 0; mi < 4; mi++)
        #pragma unroll
        for (int nj = 0; nj < 4; nj++)
            #pragma unroll
            for (int e = 0; e < 4; e++) acc[mi][nj][e] = 0.0f;

    const float* s_asq = (const float*)(smem + OFF_ASQ);
    const float* s_bsq = (const float*)(smem + OFF_BSQ);

    #pragma unroll
    for (int s = 0; s < 6; s++) {
        uint32_t ah[4][4], al[4][4], bh[4][2], bl[4][2];
        #pragma unroll
        for (int mi = 0; mi < 4; mi++) {
            uint32_t base = aAddr + mi * 16 * LDB + s * 32;
            ldsm_x4(ah[mi], base);
            ldsm_x4(al[mi], base + IMG_BYTES);
        }
        #pragma unroll
        for (int nj = 0; nj < 4; nj++) {
            uint32_t base = bAddr + nj * 8 * LDB + s * 32;
            ldsm_x2(bh[nj], base);
            ldsm_x2(bl[nj], base + IMG_BYTES);
        }
        #pragma unroll
        for (int mi = 0; mi < 4; mi++)
            #pragma unroll
            for (int nj = 0; nj < 4; nj++) {
                mma16816(acc[mi][nj], ah[mi], bh[nj]);
                mma16816(acc[mi][nj], ah[mi], bl[nj]);
                mma16816(acc[mi][nj], al[mi], bh[nj]);
            }

        if (s == 3) {
            // RBF transform: acc = 0.5 * exp(-max(asq+bsq-2*acc, 0))
            #pragma unroll
            for (int mi = 0; mi < 4; mi++) {
                float sa0 = s_asq[wm * 64 + mi * 16 + g];
                float sa1 = s_asq[wm * 64 + mi * 16 + g + 8];
                #pragma unroll
                for (int nj = 0; nj < 4; nj++) {
                    float sb0 = s_bsq[wn * 32 + nj * 8 + 2 * t];
                    float sb1 = s_bsq[wn * 32 + nj * 8 + 2 * t + 1];
                    float* A = acc[mi][nj];
                    A[0] = 0.5f * __expf(-fmaxf(fmaf(-2.0f, A[0], sa0 + sb0), 0.0f));
                    A[1] = 0.5f * __expf(-fmaxf(fmaf(-2.0f, A[1], sa0 + sb1), 0.0f));
                    A[2] = 0.5f * __expf(-fmaxf(fmaf(-2.0f, A[2], sa1 + sb0), 0.0f));
                    A[3] = 0.5f * __expf(-fmaxf(fmaf(-2.0f, A[3], sa1 + sb1), 0.0f));
                }
            }
        }
    }

    // ---- store: each lane 2 floats per (mi,nj,row-half) via STG.64 ----
    #pragma unroll
    for (int mi = 0; mi < 4; mi++) {
        size_t r0 = (size_t)(rowBase + wm * 64 + mi * 16 + g);
        #pragma unroll
        for (int nj = 0; nj < 4; nj++) {
            int c = colBase + wn * 32 + nj * 8 + 2 * t;
            float2* p0 = (float2*)(out + r0 * M + c);
            float2* p1 = (float2*)(out + (r0 + 8) * M + c);
            *p0 = make_float2(acc[mi][nj][0], acc[mi][nj][1]);
            *p1 = make_float2(acc[mi][nj][2], acc[mi][nj][3]);
        }
    }
}

// ---------------------------------------------------------------------------
extern "C" void kernel_launch(void* const* d_in, const int* in_sizes, int n_in,
                              void* d_out, int out_size)
{
    const float* a  = (const float*)d_in[0];
    const float* b  = (const float*)d_in[1];
    const float* W1 = (const float*)d_in[2];
    const float* b1 = (const float*)d_in[3];
    const float* W2 = (const float*)d_in[4];
    const float* b2 = (const float*)d_in[5];
    float* out = (float*)d_out;

    const int N = in_sizes[0] / DIM;   // 8192
    const int M = in_sizes[1] / DIM;   // 8192

    dim3 pgrid(N / 128, 2);
    prologue_kernel<<<pgrid, 128>>>(a, b, W1, b1, W2, b2);

    cudaFuncSetAttribute(gram_mma_kernel,
                         cudaFuncAttributeMaxDynamicSharedMemorySize, SMEM_DYN);
    dim3 grid(M / 128, N / 128);
    gram_mma_kernel<<<grid, 256, SMEM_DYN>>>(out, M);
}

// round 5
// speedup vs baseline: 2.3844x; 1.1671x over previous
#include <cuda_runtime.h>
#include <cuda_bf16.h>
#include <math.h>
#include <stdint.h>

#define DIM 64
#define HID 32
#define NMAX 8192
#define KTOT 96                      // 64 raw + 32 features

// ---------------------------------------------------------------------------
// Device-global scratch (allocation-free rule).
// Hi/lo bf16 split images, row-major [N][96]: k 0..63 raw, 64..95 features.
// ---------------------------------------------------------------------------
__device__ __nv_bfloat16 g_Ah[NMAX * KTOT];
__device__ __nv_bfloat16 g_Al[NMAX * KTOT];
__device__ __nv_bfloat16 g_Bh[NMAX * KTOT];
__device__ __nv_bfloat16 g_Bl[NMAX * KTOT];
__device__ float g_asq[NMAX];
__device__ float g_bsq[NMAX];

// ============================ PTX helpers (baseline ISA only) ==============
__device__ __forceinline__ uint32_t smem_u32(const void* p) {
    uint32_t a;
    asm("{ .reg .u64 t; cvta.to.shared.u64 t, %1; cvt.u32.u64 %0, t; }"
        : "=r"(a) : "l"(p));
    return a;
}
__device__ __forceinline__ void ldsm_x4(uint32_t* r, uint32_t addr) {
    asm volatile("ldmatrix.sync.aligned.m8n8.x4.shared.b16 {%0,%1,%2,%3}, [%4];"
                 : "=r"(r[0]), "=r"(r[1]), "=r"(r[2]), "=r"(r[3]) : "r"(addr));
}
__device__ __forceinline__ void ldsm_x2(uint32_t* r, uint32_t addr) {
    asm volatile("ldmatrix.sync.aligned.m8n8.x2.shared.b16 {%0,%1}, [%2];"
                 : "=r"(r[0]), "=r"(r[1]) : "r"(addr));
}
__device__ __forceinline__ void mma16816(float* d, const uint32_t* a,
                                         const uint32_t* b) {
    asm volatile(
        "mma.sync.aligned.m16n8k16.row.col.f32.bf16.bf16.f32 "
        "{%0,%1,%2,%3}, {%4,%5,%6,%7}, {%8,%9}, {%0,%1,%2,%3};"
        : "+f"(d[0]), "+f"(d[1]), "+f"(d[2]), "+f"(d[3])
        : "r"(a[0]), "r"(a[1]), "r"(a[2]), "r"(a[3]), "r"(b[0]), "r"(b[1]));
}
__device__ __forceinline__ void cp_async16(uint32_t dst, const void* src) {
    asm volatile("cp.async.cg.shared.global [%0], [%1], 16;"
                 :: "r"(dst), "l"(src) : "memory");
}
#define CP_COMMIT() asm volatile("cp.async.commit_group;" ::: "memory")
#define CP_WAIT0()  asm volatile("cp.async.wait_group 0;" ::: "memory")

// ---------------------------------------------------------------------------
// Prologue: one thread per row. asq/bsq + qmap features + hi/lo bf16 split.
// ---------------------------------------------------------------------------
__device__ __forceinline__ void split8(const float* v, uint4& h4, uint4& l4) {
    uint32_t hs[8], ls[8];
    #pragma unroll
    for (int i = 0; i < 8; i++) {
        __nv_bfloat16 h = __float2bfloat16(v[i]);
        float r = v[i] - __bfloat162float(h);
        __nv_bfloat16 l = __float2bfloat16(r);
        hs[i] = (uint32_t)__bfloat16_as_ushort(h);
        ls[i] = (uint32_t)__bfloat16_as_ushort(l);
    }
    h4.x = hs[0] | (hs[1] << 16); h4.y = hs[2] | (hs[3] << 16);
    h4.z = hs[4] | (hs[5] << 16); h4.w = hs[6] | (hs[7] << 16);
    l4.x = ls[0] | (ls[1] << 16); l4.y = ls[2] | (ls[3] << 16);
    l4.z = ls[4] | (ls[5] << 16); l4.w = ls[6] | (ls[7] << 16);
}

__global__ void prologue_kernel(const float* __restrict__ a,
                                const float* __restrict__ bmat,
                                const float* __restrict__ W1,
                                const float* __restrict__ b1,
                                const float* __restrict__ W2,
                                const float* __restrict__ b2)
{
    __shared__ float sW1t[DIM][HID];
    __shared__ float sW2t[HID][HID];
    __shared__ float sb1[HID], sb2[HID];

    const int tid = threadIdx.x;
    for (int i = tid; i < HID * DIM; i += blockDim.x) {
        int j = i / DIM, d = i % DIM;
        sW1t[d][j] = W1[i];
    }
    for (int i = tid; i < HID * HID; i += blockDim.x) {
        int j = i / HID, k = i % HID;
        sW2t[k][j] = W2[i];
    }
    if (tid < HID) { sb1[tid] = b1[tid]; sb2[tid] = b2[tid]; }
    __syncthreads();

    const int side = blockIdx.y;
    const float* __restrict__ x = side ? bmat : a;
    const float scale = side ? 1.0f : 0.5f;   // fold quantum weight into fa
    const int row = blockIdx.x * blockDim.x + tid;

    float v[DIM];
    const float4* xr = (const float4*)(x + (size_t)row * DIM);
    #pragma unroll
    for (int q = 0; q < DIM / 4; q++) {
        float4 t = xr[q];
        v[4 * q + 0] = t.x; v[4 * q + 1] = t.y;
        v[4 * q + 2] = t.z; v[4 * q + 3] = t.w;
    }

    float s = 0.0f;
    #pragma unroll
    for (int d = 0; d < DIM; d++) s = fmaf(v[d], v[d], s);
    if (side) g_bsq[row] = s; else g_asq[row] = s;

    float h[HID];
    #pragma unroll
    for (int j = 0; j < HID; j++) h[j] = sb1[j];
    #pragma unroll
    for (int d = 0; d < DIM; d++)
        #pragma unroll
        for (int j = 0; j < HID; j++)
            h[j] = fmaf(v[d], sW1t[d][j], h[j]);
    #pragma unroll
    for (int j = 0; j < HID; j++) h[j] = tanhf(h[j]);

    float o[HID];
    #pragma unroll
    for (int j = 0; j < HID; j++) o[j] = sb2[j];
    #pragma unroll
    for (int k = 0; k < HID; k++)
        #pragma unroll
        for (int j = 0; j < HID; j++)
            o[j] = fmaf(h[k], sW2t[k][j], o[j]);
    #pragma unroll
    for (int j = 0; j < HID; j++) o[j] *= scale;

    uint4* dh = (uint4*)((side ? g_Bh : g_Ah) + (size_t)row * KTOT);
    uint4* dl = (uint4*)((side ? g_Bl : g_Al) + (size_t)row * KTOT);
    #pragma unroll
    for (int c = 0; c < 8; c++) {            // raw, k 0..63
        uint4 h4, l4;
        split8(&v[c * 8], h4, l4);
        dh[c] = h4; dl[c] = l4;
    }
    #pragma unroll
    for (int c = 0; c < 4; c++) {            // features, k 64..95
        uint4 h4, l4;
        split8(&o[c * 8], h4, l4);
        dh[8 + c] = h4; dl[8 + c] = l4;
    }
}

// ---------------------------------------------------------------------------
// Streaming Gram kernel. grid = 148 persistent-ish CTAs; each owns a
// contiguous row-major band of the 64x64 tile grid. A images loaded per row
// segment; B images double-buffered via cp.async, prefetched one tile ahead.
// ---------------------------------------------------------------------------
#define LDB 208                       // smem row stride bytes (104 bf16)
#define IMG_BYTES (128 * LDB)         // 26624
#define A_BYTES   (2 * IMG_BYTES)     // Ah + Al
#define OFF_A     0
#define OFF_ASQ   A_BYTES             // 512 bytes
#define OFF_STAGE0 (A_BYTES + 512)
#define OFF_BSQ_ST (2 * IMG_BYTES)    // within a stage
#define STAGE_STRIDE (2 * IMG_BYTES + 1024)   // 54272
#define SMEM_DYN (OFF_STAGE0 + 2 * STAGE_STRIDE)  // 162304
#define GRID_CTAS 148

__global__ __launch_bounds__(256, 1)
void gram_mma_kernel(float* __restrict__ out, int M, int tilesR, int tilesC)
{
    extern __shared__ char smem[];
    const uint32_t sb = smem_u32(smem);
    const int tid = threadIdx.x;
    const int wid = tid >> 5, lane = tid & 31;

    const int total = tilesR * tilesC;
    const int cid = blockIdx.x;
    const int start = (int)(((long long)cid * total) / gridDim.x);
    const int end   = (int)(((long long)(cid + 1) * total) / gridDim.x);
    if (start >= end) return;

    // ---- helpers (lambdas) ----
    auto loadA = [&](int rowTile) {
        const int rowBase = rowTile * 128;
        const uint4* srcH = (const uint4*)(g_Ah + (size_t)rowBase * KTOT);
        const uint4* srcL = (const uint4*)(g_Al + (size_t)rowBase * KTOT);
        uint4* dst = (uint4*)smem;
        #pragma unroll
        for (int i = 0; i < 6; i++) {
            int lin = tid + i * 256;          // 0..1535
            int r = lin / 12, c = lin % 12;
            dst[r * 13 + c] = srcH[lin];
            dst[(IMG_BYTES / 16) + r * 13 + c] = srcL[lin];
        }
        if (tid < 128)
            ((float*)(smem + OFF_ASQ))[tid] = g_asq[rowBase + tid];
    };
    auto copyB = [&](int colTile, int stage) {
        const int colBase = colTile * 128;
        const char* srcH = (const char*)(g_Bh + (size_t)colBase * KTOT);
        const char* srcL = (const char*)(g_Bl + (size_t)colBase * KTOT);
        const uint32_t stBase = sb + OFF_STAGE0 + stage * STAGE_STRIDE;
        #pragma unroll
        for (int i = 0; i < 6; i++) {
            int lin = tid + i * 256;          // 0..1535
            int r = lin / 12, c = lin % 12;
            uint32_t doff = (uint32_t)(r * 13 + c) * 16;
            cp_async16(stBase + doff, srcH + lin * 16);
            cp_async16(stBase + IMG_BYTES + doff, srcL + lin * 16);
        }
        if (tid < 32)
            cp_async16(stBase + OFF_BSQ_ST + tid * 16,
                       (const char*)(g_bsq + colBase) + tid * 16);
    };

    const int wm = wid >> 2, wn = wid & 3;   // warp grid 2 x 4
    const int g = lane >> 2, t = lane & 3;
    const uint32_t aAddr = sb + OFF_A +
        (wm * 64 + (lane & 15)) * LDB + (lane >> 4) * 16;
    const uint32_t bLane = (wn * 32 + (lane & 7)) * LDB + ((lane >> 3) & 1) * 16;
    const float* s_asq = (const float*)(smem + OFF_ASQ);

    // ---- prologue: A for first row, prefetch B(start) ----
    int curRow = start / tilesC;
    loadA(curRow);
    copyB(start % tilesC, 0);
    CP_COMMIT();
    __syncthreads();

    for (int tt = start; tt < end; tt++) {
        const int stage = (tt - start) & 1;
        const int rt = tt / tilesC, ct = tt - rt * tilesC;
        const int rowBase = rt * 128, colBase = ct * 128;

        CP_WAIT0();
        __syncthreads();

        if (tt + 1 < end)
            copyB((tt + 1) % tilesC, stage ^ 1);
        CP_COMMIT();

        if (rt != curRow) {
            loadA(rt);
            curRow = rt;
            __syncthreads();
        }

        const uint32_t stBase = sb + OFF_STAGE0 + stage * STAGE_STRIDE;
        const uint32_t bAddr = stBase + bLane;
        const float* s_bsq = (const float*)(smem + OFF_STAGE0 +
                                            stage * STAGE_STRIDE + OFF_BSQ_ST);

        float acc[4][4][4];
        #pragma unroll
        for (int mi = 0; mi < 4; mi++)
            #pragma unroll
            for (int nj = 0; nj < 4; nj++)
                #pragma unroll
                for (int e = 0; e < 4; e++) acc[mi][nj][e] = 0.0f;

        #pragma unroll
        for (int s = 0; s < 6; s++) {
            uint32_t ah[4][4], al[4][4], bh[4][2], bl[4][2];
            #pragma unroll
            for (int mi = 0; mi < 4; mi++) {
                uint32_t base = aAddr + mi * 16 * LDB + s * 32;
                ldsm_x4(ah[mi], base);
                ldsm_x4(al[mi], base + IMG_BYTES);
            }
            #pragma unroll
            for (int nj = 0; nj < 4; nj++) {
                uint32_t base = bAddr + nj * 8 * LDB + s * 32;
                ldsm_x2(bh[nj], base);
                ldsm_x2(bl[nj], base + IMG_BYTES);
            }
            #pragma unroll
            for (int mi = 0; mi < 4; mi++)
                #pragma unroll
                for (int nj = 0; nj < 4; nj++) {
                    mma16816(acc[mi][nj], ah[mi], bh[nj]);
                    mma16816(acc[mi][nj], ah[mi], bl[nj]);
                    mma16816(acc[mi][nj], al[mi], bh[nj]);
                }

            if (s == 3) {
                // RBF transform: acc = 0.5 * exp(-max(asq+bsq-2*acc, 0))
                #pragma unroll
                for (int mi = 0; mi < 4; mi++) {
                    float sa0 = s_asq[wm * 64 + mi * 16 + g];
                    float sa1 = s_asq[wm * 64 + mi * 16 + g + 8];
                    #pragma unroll
                    for (int nj = 0; nj < 4; nj++) {
                        float sb0 = s_bsq[wn * 32 + nj * 8 + 2 * t];
                        float sb1 = s_bsq[wn * 32 + nj * 8 + 2 * t + 1];
                        float* A = acc[mi][nj];
                        A[0] = 0.5f * __expf(-fmaxf(fmaf(-2.0f, A[0], sa0 + sb0), 0.0f));
                        A[1] = 0.5f * __expf(-fmaxf(fmaf(-2.0f, A[1], sa0 + sb1), 0.0f));
                        A[2] = 0.5f * __expf(-fmaxf(fmaf(-2.0f, A[2], sa1 + sb0), 0.0f));
                        A[3] = 0.5f * __expf(-fmaxf(fmaf(-2.0f, A[3], sa1 + sb1), 0.0f));
                    }
                }
            }
        }

        // ---- store ----
        #pragma unroll
        for (int mi = 0; mi < 4; mi++) {
            size_t r0 = (size_t)(rowBase + wm * 64 + mi * 16 + g);
            #pragma unroll
            for (int nj = 0; nj < 4; nj++) {
                int c = colBase + wn * 32 + nj * 8 + 2 * t;
                float2* p0 = (float2*)(out + r0 * M + c);
                float2* p1 = (float2*)(out + (r0 + 8) * M + c);
                *p0 = make_float2(acc[mi][nj][0], acc[mi][nj][1]);
                *p1 = make_float2(acc[mi][nj][2], acc[mi][nj][3]);
            }
        }
    }
}

// ---------------------------------------------------------------------------
extern "C" void kernel_launch(void* const* d_in, const int* in_sizes, int n_in,
                              void* d_out, int out_size)
{
    const float* a  = (const float*)d_in[0];
    const float* b  = (const float*)d_in[1];
    const float* W1 = (const float*)d_in[2];
    const float* b1 = (const float*)d_in[3];
    const float* W2 = (const float*)d_in[4];
    const float* b2 = (const float*)d_in[5];
    float* out = (float*)d_out;

    const int N = in_sizes[0] / DIM;   // 8192
    const int M = in_sizes[1] / DIM;   // 8192

    dim3 pgrid(N / 128, 2);
    prologue_kernel<<<pgrid, 128>>>(a, b, W1, b1, W2, b2);

    cudaFuncSetAttribute(gram_mma_kernel,
                         cudaFuncAttributeMaxDynamicSharedMemorySize, SMEM_DYN);
    gram_mma_kernel<<<GRID_CTAS, 256, SMEM_DYN>>>(out, M, N / 128, M / 128);
}

// round 6
// speedup vs baseline: 2.4810x; 1.0405x over previous
#include <cuda_runtime.h>
#include <cuda_bf16.h>
#include <math.h>
#include <stdint.h>

#define DIM 64
#define HID 32
#define NMAX 8192
#define KTOT 96                      // 64 raw + 32 features

// ---------------------------------------------------------------------------
// Device-global scratch (allocation-free rule).
// Hi/lo bf16 split images, row-major [N][96]: k 0..63 raw, 64..95 features.
// ---------------------------------------------------------------------------
__device__ __nv_bfloat16 g_Ah[NMAX * KTOT];
__device__ __nv_bfloat16 g_Al[NMAX * KTOT];
__device__ __nv_bfloat16 g_Bh[NMAX * KTOT];
__device__ __nv_bfloat16 g_Bl[NMAX * KTOT];
__device__ float g_asq[NMAX];
__device__ float g_bsq[NMAX];

// ============================ PTX helpers (baseline ISA only) ==============
__device__ __forceinline__ uint32_t smem_u32(const void* p) {
    uint32_t a;
    asm("{ .reg .u64 t; cvta.to.shared.u64 t, %1; cvt.u32.u64 %0, t; }"
        : "=r"(a) : "l"(p));
    return a;
}
__device__ __forceinline__ void ldsm_x4(uint32_t* r, uint32_t addr) {
    asm volatile("ldmatrix.sync.aligned.m8n8.x4.shared.b16 {%0,%1,%2,%3}, [%4];"
                 : "=r"(r[0]), "=r"(r[1]), "=r"(r[2]), "=r"(r[3]) : "r"(addr));
}
__device__ __forceinline__ void ldsm_x2(uint32_t* r, uint32_t addr) {
    asm volatile("ldmatrix.sync.aligned.m8n8.x2.shared.b16 {%0,%1}, [%2];"
                 : "=r"(r[0]), "=r"(r[1]) : "r"(addr));
}
__device__ __forceinline__ void mma16816(float* d, const uint32_t* a,
                                         const uint32_t* b) {
    asm volatile(
        "mma.sync.aligned.m16n8k16.row.col.f32.bf16.bf16.f32 "
        "{%0,%1,%2,%3}, {%4,%5,%6,%7}, {%8,%9}, {%0,%1,%2,%3};"
        : "+f"(d[0]), "+f"(d[1]), "+f"(d[2]), "+f"(d[3])
        : "r"(a[0]), "r"(a[1]), "r"(a[2]), "r"(a[3]), "r"(b[0]), "r"(b[1]));
}
__device__ __forceinline__ void cp_async16(uint32_t dst, const void* src) {
    asm volatile("cp.async.cg.shared.global [%0], [%1], 16;"
                 :: "r"(dst), "l"(src) : "memory");
}
#define CP_COMMIT() asm volatile("cp.async.commit_group;" ::: "memory")
#define CP_WAIT0()  asm volatile("cp.async.wait_group 0;" ::: "memory")
__device__ __forceinline__ void stg_cs_v2(float* p, float x, float y) {
    asm volatile("st.global.cs.v2.f32 [%0], {%1, %2};"
                 :: "l"(p), "f"(x), "f"(y) : "memory");
}

// ---------------------------------------------------------------------------
// Prologue: one thread per row. asq/bsq + qmap features + hi/lo bf16 split.
// ---------------------------------------------------------------------------
__device__ __forceinline__ void split8(const float* v, uint4& h4, uint4& l4) {
    uint32_t hs[8], ls[8];
    #pragma unroll
    for (int i = 0; i < 8; i++) {
        __nv_bfloat16 h = __float2bfloat16(v[i]);
        float r = v[i] - __bfloat162float(h);
        __nv_bfloat16 l = __float2bfloat16(r);
        hs[i] = (uint32_t)__bfloat16_as_ushort(h);
        ls[i] = (uint32_t)__bfloat16_as_ushort(l);
    }
    h4.x = hs[0] | (hs[1] << 16); h4.y = hs[2] | (hs[3] << 16);
    h4.z = hs[4] | (hs[5] << 16); h4.w = hs[6] | (hs[7] << 16);
    l4.x = ls[0] | (ls[1] << 16); l4.y = ls[2] | (ls[3] << 16);
    l4.z = ls[4] | (ls[5] << 16); l4.w = ls[6] | (ls[7] << 16);
}

__global__ void prologue_kernel(const float* __restrict__ a,
                                const float* __restrict__ bmat,
                                const float* __restrict__ W1,
                                const float* __restrict__ b1,
                                const float* __restrict__ W2,
                                const float* __restrict__ b2)
{
    __shared__ float sW1t[DIM][HID];
    __shared__ float sW2t[HID][HID];
    __shared__ float sb1[HID], sb2[HID];

    const int tid = threadIdx.x;
    for (int i = tid; i < HID * DIM; i += blockDim.x) {
        int j = i / DIM, d = i % DIM;
        sW1t[d][j] = W1[i];
    }
    for (int i = tid; i < HID * HID; i += blockDim.x) {
        int j = i / HID, k = i % HID;
        sW2t[k][j] = W2[i];
    }
    if (tid < HID) { sb1[tid] = b1[tid]; sb2[tid] = b2[tid]; }
    __syncthreads();

    const int side = blockIdx.y;
    const float* __restrict__ x = side ? bmat : a;
    const float scale = side ? 1.0f : 0.5f;   // fold quantum weight into fa
    const int row = blockIdx.x * blockDim.x + tid;

    float v[DIM];
    const float4* xr = (const float4*)(x + (size_t)row * DIM);
    #pragma unroll
    for (int q = 0; q < DIM / 4; q++) {
        float4 t = xr[q];
        v[4 * q + 0] = t.x; v[4 * q + 1] = t.y;
        v[4 * q + 2] = t.z; v[4 * q + 3] = t.w;
    }

    float s = 0.0f;
    #pragma unroll
    for (int d = 0; d < DIM; d++) s = fmaf(v[d], v[d], s);
    if (side) g_bsq[row] = s; else g_asq[row] = s;

    float h[HID];
    #pragma unroll
    for (int j = 0; j < HID; j++) h[j] = sb1[j];
    #pragma unroll
    for (int d = 0; d < DIM; d++)
        #pragma unroll
        for (int j = 0; j < HID; j++)
            h[j] = fmaf(v[d], sW1t[d][j], h[j]);
    #pragma unroll
    for (int j = 0; j < HID; j++) h[j] = tanhf(h[j]);

    float o[HID];
    #pragma unroll
    for (int j = 0; j < HID; j++) o[j] = sb2[j];
    #pragma unroll
    for (int k = 0; k < HID; k++)
        #pragma unroll
        for (int j = 0; j < HID; j++)
            o[j] = fmaf(h[k], sW2t[k][j], o[j]);
    #pragma unroll
    for (int j = 0; j < HID; j++) o[j] *= scale;

    uint4* dh = (uint4*)((side ? g_Bh : g_Ah) + (size_t)row * KTOT);
    uint4* dl = (uint4*)((side ? g_Bl : g_Al) + (size_t)row * KTOT);
    #pragma unroll
    for (int c = 0; c < 8; c++) {            // raw, k 0..63
        uint4 h4, l4;
        split8(&v[c * 8], h4, l4);
        dh[c] = h4; dl[c] = l4;
    }
    #pragma unroll
    for (int c = 0; c < 4; c++) {            // features, k 64..95
        uint4 h4, l4;
        split8(&o[c * 8], h4, l4);
        dh[8 + c] = h4; dl[8 + c] = l4;
    }
}

// ---------------------------------------------------------------------------
// Streaming Gram kernel. 148 CTAs x 512 threads (4x4 warp grid, 32x32 warp
// tile). Each CTA owns a contiguous row-major band of the 64x64 tile grid.
// A images per row segment; B images double-buffered via cp.async.
// ---------------------------------------------------------------------------
#define LDB 208                       // smem row stride bytes (104 bf16)
#define IMG_BYTES (128 * LDB)         // 26624
#define A_BYTES   (2 * IMG_BYTES)     // Ah + Al
#define OFF_A     0
#define OFF_ASQ   A_BYTES             // 512 bytes
#define OFF_STAGE0 (A_BYTES + 512)
#define OFF_BSQ_ST (2 * IMG_BYTES)    // within a stage
#define STAGE_STRIDE (2 * IMG_BYTES + 1024)   // 54272
#define SMEM_DYN (OFF_STAGE0 + 2 * STAGE_STRIDE)  // 162304
#define GRID_CTAS 148
#define NTHREADS 512

__global__ __launch_bounds__(NTHREADS, 1)
void gram_mma_kernel(float* __restrict__ out, int M, int tilesR, int tilesC)
{
    extern __shared__ char smem[];
    const uint32_t sb = smem_u32(smem);
    const int tid = threadIdx.x;
    const int wid = tid >> 5, lane = tid & 31;

    const int total = tilesR * tilesC;
    const int cid = blockIdx.x;
    const int start = (int)(((long long)cid * total) / gridDim.x);
    const int end   = (int)(((long long)(cid + 1) * total) / gridDim.x);
    if (start >= end) return;

    auto loadA = [&](int rowTile) {
        const int rowBase = rowTile * 128;
        const uint4* srcH = (const uint4*)(g_Ah + (size_t)rowBase * KTOT);
        const uint4* srcL = (const uint4*)(g_Al + (size_t)rowBase * KTOT);
        uint4* dst = (uint4*)smem;
        #pragma unroll
        for (int i = 0; i < 3; i++) {
            int lin = tid + i * NTHREADS;     // 0..1535
            int r = lin / 12, c = lin % 12;
            dst[r * 13 + c] = srcH[lin];
            dst[(IMG_BYTES / 16) + r * 13 + c] = srcL[lin];
        }
        if (tid < 128)
            ((float*)(smem + OFF_ASQ))[tid] = g_asq[rowBase + tid];
    };
    auto copyB = [&](int colTile, int stage) {
        const int colBase = colTile * 128;
        const char* srcH = (const char*)(g_Bh + (size_t)colBase * KTOT);
        const char* srcL = (const char*)(g_Bl + (size_t)colBase * KTOT);
        const uint32_t stBase = sb + OFF_STAGE0 + stage * STAGE_STRIDE;
        #pragma unroll
        for (int i = 0; i < 3; i++) {
            int lin = tid + i * NTHREADS;     // 0..1535
            int r = lin / 12, c = lin % 12;
            uint32_t doff = (uint32_t)(r * 13 + c) * 16;
            cp_async16(stBase + doff, srcH + lin * 16);
            cp_async16(stBase + IMG_BYTES + doff, srcL + lin * 16);
        }
        if (tid < 32)
            cp_async16(stBase + OFF_BSQ_ST + tid * 16,
                       (const char*)(g_bsq + colBase) + tid * 16);
    };

    const int wm = wid >> 2, wn = wid & 3;   // warp grid 4 x 4
    const int g = lane >> 2, t = lane & 3;
    const uint32_t aAddr = sb + OFF_A +
        (wm * 32 + (lane & 15)) * LDB + (lane >> 4) * 16;
    const uint32_t bLane = (wn * 32 + (lane & 7)) * LDB + ((lane >> 3) & 1) * 16;
    const float* s_asq = (const float*)(smem + OFF_ASQ);

    int curRow = start / tilesC;
    loadA(curRow);
    copyB(start % tilesC, 0);
    CP_COMMIT();
    __syncthreads();

    for (int tt = start; tt < end; tt++) {
        const int stage = (tt - start) & 1;
        const int rt = tt / tilesC, ct = tt - rt * tilesC;
        const int rowBase = rt * 128, colBase = ct * 128;

        CP_WAIT0();
        __syncthreads();

        if (tt + 1 < end)
            copyB((tt + 1) % tilesC, stage ^ 1);
        CP_COMMIT();

        if (rt != curRow) {
            loadA(rt);
            curRow = rt;
            __syncthreads();
        }

        const uint32_t stBase = sb + OFF_STAGE0 + stage * STAGE_STRIDE;
        const uint32_t bAddr = stBase + bLane;
        const float* s_bsq = (const float*)(smem + OFF_STAGE0 +
                                            stage * STAGE_STRIDE + OFF_BSQ_ST);

        float acc[2][4][4];
        #pragma unroll
        for (int mi = 0; mi < 2; mi++)
            #pragma unroll
            for (int nj = 0; nj < 4; nj++)
                #pragma unroll
                for (int e = 0; e < 4; e++) acc[mi][nj][e] = 0.0f;

        #pragma unroll
        for (int s = 0; s < 6; s++) {
            uint32_t ah[2][4], al[2][4], bh[4][2], bl[4][2];
            #pragma unroll
            for (int mi = 0; mi < 2; mi++) {
                uint32_t base = aAddr + mi * 16 * LDB + s * 32;
                ldsm_x4(ah[mi], base);
                ldsm_x4(al[mi], base + IMG_BYTES);
            }
            #pragma unroll
            for (int nj = 0; nj < 4; nj++) {
                uint32_t base = bAddr + nj * 8 * LDB + s * 32;
                ldsm_x2(bh[nj], base);
                ldsm_x2(bl[nj], base + IMG_BYTES);
            }
            #pragma unroll
            for (int mi = 0; mi < 2; mi++)
                #pragma unroll
                for (int nj = 0; nj < 4; nj++) {
                    mma16816(acc[mi][nj], ah[mi], bh[nj]);
                    mma16816(acc[mi][nj], ah[mi], bl[nj]);
                    mma16816(acc[mi][nj], al[mi], bh[nj]);
                }

            if (s == 3) {
                // RBF transform: acc = 0.5 * exp(-max(asq+bsq-2*acc, 0))
                #pragma unroll
                for (int mi = 0; mi < 2; mi++) {
                    float sa0 = s_asq[wm * 32 + mi * 16 + g];
                    float sa1 = s_asq[wm * 32 + mi * 16 + g + 8];
                    #pragma unroll
                    for (int nj = 0; nj < 4; nj++) {
                        float sb0 = s_bsq[wn * 32 + nj * 8 + 2 * t];
                        float sb1 = s_bsq[wn * 32 + nj * 8 + 2 * t + 1];
                        float* A = acc[mi][nj];
                        A[0] = 0.5f * __expf(-fmaxf(fmaf(-2.0f, A[0], sa0 + sb0), 0.0f));
                        A[1] = 0.5f * __expf(-fmaxf(fmaf(-2.0f, A[1], sa0 + sb1), 0.0f));
                        A[2] = 0.5f * __expf(-fmaxf(fmaf(-2.0f, A[2], sa1 + sb0), 0.0f));
                        A[3] = 0.5f * __expf(-fmaxf(fmaf(-2.0f, A[3], sa1 + sb1), 0.0f));
                    }
                }
            }
        }

        // ---- store (streaming; output never re-read) ----
        #pragma unroll
        for (int mi = 0; mi < 2; mi++) {
            size_t r0 = (size_t)(rowBase + wm * 32 + mi * 16 + g);
            #pragma unroll
            for (int nj = 0; nj < 4; nj++) {
                int c = colBase + wn * 32 + nj * 8 + 2 * t;
                stg_cs_v2(out + r0 * M + c, acc[mi][nj][0], acc[mi][nj][1]);
                stg_cs_v2(out + (r0 + 8) * M + c, acc[mi][nj][2], acc[mi][nj][3]);
            }
        }
    }
}

// ---------------------------------------------------------------------------
extern "C" void kernel_launch(void* const* d_in, const int* in_sizes, int n_in,
                              void* d_out, int out_size)
{
    const float* a  = (const float*)d_in[0];
    const float* b  = (const float*)d_in[1];
    const float* W1 = (const float*)d_in[2];
    const float* b1 = (const float*)d_in[3];
    const float* W2 = (const float*)d_in[4];
    const float* b2 = (const float*)d_in[5];
    float* out = (float*)d_out;

    const int N = in_sizes[0] / DIM;   // 8192
    const int M = in_sizes[1] / DIM;   // 8192

    dim3 pgrid(N / 128, 2);
    prologue_kernel<<<pgrid, 128>>>(a, b, W1, b1, W2, b2);

    cudaFuncSetAttribute(gram_mma_kernel,
                         cudaFuncAttributeMaxDynamicSharedMemorySize, SMEM_DYN);
    gram_mma_kernel<<<GRID_CTAS, NTHREADS, SMEM_DYN>>>(out, M, N / 128, M / 128);
}

// round 7
// speedup vs baseline: 2.4821x; 1.0004x over previous
#include <cuda_runtime.h>
#include <cuda_bf16.h>
#include <math.h>
#include <stdint.h>

#define DIM 64
#define HID 32
#define NMAX 8192
#define KTOT 96                      // 64 raw + 32 features

// ---------------------------------------------------------------------------
// Device-global scratch (allocation-free rule).
// Hi/lo bf16 split images, row-major [N][96]: k 0..63 raw, 64..95 features.
// ---------------------------------------------------------------------------
__device__ __nv_bfloat16 g_Ah[NMAX * KTOT];
__device__ __nv_bfloat16 g_Al[NMAX * KTOT];
__device__ __nv_bfloat16 g_Bh[NMAX * KTOT];
__device__ __nv_bfloat16 g_Bl[NMAX * KTOT];
__device__ float g_asq[NMAX];
__device__ float g_bsq[NMAX];

// ============================ PTX helpers (baseline ISA only) ==============
__device__ __forceinline__ uint32_t smem_u32(const void* p) {
    uint32_t a;
    asm("{ .reg .u64 t; cvta.to.shared.u64 t, %1; cvt.u32.u64 %0, t; }"
        : "=r"(a) : "l"(p));
    return a;
}
__device__ __forceinline__ void ldsm_x4(uint32_t* r, uint32_t addr) {
    asm volatile("ldmatrix.sync.aligned.m8n8.x4.shared.b16 {%0,%1,%2,%3}, [%4];"
                 : "=r"(r[0]), "=r"(r[1]), "=r"(r[2]), "=r"(r[3]) : "r"(addr));
}
__device__ __forceinline__ void mma16816(float* d, const uint32_t* a,
                                         const uint32_t* b) {
    asm volatile(
        "mma.sync.aligned.m16n8k16.row.col.f32.bf16.bf16.f32 "
        "{%0,%1,%2,%3}, {%4,%5,%6,%7}, {%8,%9}, {%0,%1,%2,%3};"
        : "+f"(d[0]), "+f"(d[1]), "+f"(d[2]), "+f"(d[3])
        : "r"(a[0]), "r"(a[1]), "r"(a[2]), "r"(a[3]), "r"(b[0]), "r"(b[1]));
}
__device__ __forceinline__ void cp_async16(uint32_t dst, const void* src) {
    asm volatile("cp.async.cg.shared.global [%0], [%1], 16;"
                 :: "r"(dst), "l"(src) : "memory");
}
#define CP_COMMIT() asm volatile("cp.async.commit_group;" ::: "memory")
#define CP_WAIT0()  asm volatile("cp.async.wait_group 0;" ::: "memory")
__device__ __forceinline__ void stg_cs_v2(float* p, float x, float y) {
    asm volatile("st.global.cs.v2.f32 [%0], {%1, %2};"
                 :: "l"(p), "f"(x), "f"(y) : "memory");
}
__device__ __forceinline__ float ex2f(float x) {
    float r;
    asm("ex2.approx.f32 %0, %1;" : "=f"(r) : "f"(x));
    return r;
}

// ---------------------------------------------------------------------------
// Prologue: one thread per row. asq/bsq + qmap features + hi/lo bf16 split.
// ---------------------------------------------------------------------------
__device__ __forceinline__ void split8(const float* v, uint4& h4, uint4& l4) {
    uint32_t hs[8], ls[8];
    #pragma unroll
    for (int i = 0; i < 8; i++) {
        __nv_bfloat16 h = __float2bfloat16(v[i]);
        float r = v[i] - __bfloat162float(h);
        __nv_bfloat16 l = __float2bfloat16(r);
        hs[i] = (uint32_t)__bfloat16_as_ushort(h);
        ls[i] = (uint32_t)__bfloat16_as_ushort(l);
    }
    h4.x = hs[0] | (hs[1] << 16); h4.y = hs[2] | (hs[3] << 16);
    h4.z = hs[4] | (hs[5] << 16); h4.w = hs[6] | (hs[7] << 16);
    l4.x = ls[0] | (ls[1] << 16); l4.y = ls[2] | (ls[3] << 16);
    l4.z = ls[4] | (ls[5] << 16); l4.w = ls[6] | (ls[7] << 16);
}

__global__ void prologue_kernel(const float* __restrict__ a,
                                const float* __restrict__ bmat,
                                const float* __restrict__ W1,
                                const float* __restrict__ b1,
                                const float* __restrict__ W2,
                                const float* __restrict__ b2)
{
    __shared__ float sW1t[DIM][HID];
    __shared__ float sW2t[HID][HID];
    __shared__ float sb1[HID], sb2[HID];

    const int tid = threadIdx.x;
    for (int i = tid; i < HID * DIM; i += blockDim.x) {
        int j = i / DIM, d = i % DIM;
        sW1t[d][j] = W1[i];
    }
    for (int i = tid; i < HID * HID; i += blockDim.x) {
        int j = i / HID, k = i % HID;
        sW2t[k][j] = W2[i];
    }
    if (tid < HID) { sb1[tid] = b1[tid]; sb2[tid] = b2[tid]; }
    __syncthreads();

    const int side = blockIdx.y;
    const float* __restrict__ x = side ? bmat : a;
    const float scale = side ? 1.0f : 0.5f;   // fold quantum weight into fa
    const int row = blockIdx.x * blockDim.x + tid;

    float v[DIM];
    const float4* xr = (const float4*)(x + (size_t)row * DIM);
    #pragma unroll
    for (int q = 0; q < DIM / 4; q++) {
        float4 t = xr[q];
        v[4 * q + 0] = t.x; v[4 * q + 1] = t.y;
        v[4 * q + 2] = t.z; v[4 * q + 3] = t.w;
    }

    float s = 0.0f;
    #pragma unroll
    for (int d = 0; d < DIM; d++) s = fmaf(v[d], v[d], s);
    if (side) g_bsq[row] = s; else g_asq[row] = s;

    float h[HID];
    #pragma unroll
    for (int j = 0; j < HID; j++) h[j] = sb1[j];
    #pragma unroll
    for (int d = 0; d < DIM; d++)
        #pragma unroll
        for (int j = 0; j < HID; j++)
            h[j] = fmaf(v[d], sW1t[d][j], h[j]);
    #pragma unroll
    for (int j = 0; j < HID; j++) h[j] = tanhf(h[j]);

    float o[HID];
    #pragma unroll
    for (int j = 0; j < HID; j++) o[j] = sb2[j];
    #pragma unroll
    for (int k = 0; k < HID; k++)
        #pragma unroll
        for (int j = 0; j < HID; j++)
            o[j] = fmaf(h[k], sW2t[k][j], o[j]);
    #pragma unroll
    for (int j = 0; j < HID; j++) o[j] *= scale;

    uint4* dh = (uint4*)((side ? g_Bh : g_Ah) + (size_t)row * KTOT);
    uint4* dl = (uint4*)((side ? g_Bl : g_Al) + (size_t)row * KTOT);
    #pragma unroll
    for (int c = 0; c < 8; c++) {            // raw, k 0..63
        uint4 h4, l4;
        split8(&v[c * 8], h4, l4);
        dh[c] = h4; dl[c] = l4;
    }
    #pragma unroll
    for (int c = 0; c < 4; c++) {            // features, k 64..95
        uint4 h4, l4;
        split8(&o[c * 8], h4, l4);
        dh[8 + c] = h4; dl[8 + c] = l4;
    }
}

// ---------------------------------------------------------------------------
// Streaming Gram kernel. 148 CTAs x 512 threads (4x4 warp grid, 32x32 warp
// tile). A per row segment; B double-buffered via cp.async. B fragments via
// ldsm_x4 over nj-pairs. RBF transform interleaved with feature MMAs.
// ---------------------------------------------------------------------------
#define LDB 208                       // smem row stride bytes (104 bf16)
#define IMG_BYTES (128 * LDB)         // 26624
#define A_BYTES   (2 * IMG_BYTES)     // Ah + Al
#define OFF_A     0
#define OFF_ASQ   A_BYTES             // 512 bytes
#define OFF_STAGE0 (A_BYTES + 512)
#define OFF_BSQ_ST (2 * IMG_BYTES)    // within a stage
#define STAGE_STRIDE (2 * IMG_BYTES + 1024)   // 54272
#define SMEM_DYN (OFF_STAGE0 + 2 * STAGE_STRIDE)  // 162304
#define GRID_CTAS 148
#define NTHREADS 512
#define TWO_L2E 2.8853900817779268f   // 2*log2(e)
#define NL2E    1.4426950408889634f   // log2(e)

// load all fragments for k-step S of the current tile
#define LOAD_FRAGS(S, AH, AL, BH, BL) do {                                    \
    _Pragma("unroll")                                                         \
    for (int mi = 0; mi < 2; mi++) {                                          \
        uint32_t base = aAddr + mi * 16 * LDB + (S) * 32;                     \
        ldsm_x4((AH)[mi], base);                                              \
        ldsm_x4((AL)[mi], base + IMG_BYTES);                                  \
    }                                                                         \
    _Pragma("unroll")                                                         \
    for (int p = 0; p < 2; p++) {                                             \
        uint32_t base = bAddr + p * 16 * LDB + (S) * 32;                      \
        ldsm_x4((BH)[p], base);                                               \
        ldsm_x4((BL)[p], base + IMG_BYTES);                                   \
    }                                                                         \
} while (0)

// 3-pass MMA for one nj-pair p against all mi
#define MMA_PAIR(P, AH, AL, BH, BL) do {                                      \
    _Pragma("unroll")                                                         \
    for (int mi = 0; mi < 2; mi++) {                                          \
        mma16816(acc[mi][2 * (P)],     (AH)[mi], &(BH)[P][0]);                \
        mma16816(acc[mi][2 * (P) + 1], (AH)[mi], &(BH)[P][2]);                \
        mma16816(acc[mi][2 * (P)],     (AH)[mi], &(BL)[P][0]);                \
        mma16816(acc[mi][2 * (P) + 1], (AH)[mi], &(BL)[P][2]);                \
        mma16816(acc[mi][2 * (P)],     (AL)[mi], &(BH)[P][0]);                \
        mma16816(acc[mi][2 * (P) + 1], (AL)[mi], &(BH)[P][2]);                \
    }                                                                         \
} while (0)

__global__ __launch_bounds__(NTHREADS, 1)
void gram_mma_kernel(float* __restrict__ out, int M, int tilesR, int tilesC)
{
    extern __shared__ char smem[];
    const uint32_t sb = smem_u32(smem);
    const int tid = threadIdx.x;
    const int wid = tid >> 5, lane = tid & 31;

    const int total = tilesR * tilesC;
    const int cid = blockIdx.x;
    const int start = (int)(((long long)cid * total) / gridDim.x);
    const int end   = (int)(((long long)(cid + 1) * total) / gridDim.x);
    if (start >= end) return;

    auto loadA = [&](int rowTile) {
        const int rowBase = rowTile * 128;
        const uint4* srcH = (const uint4*)(g_Ah + (size_t)rowBase * KTOT);
        const uint4* srcL = (const uint4*)(g_Al + (size_t)rowBase * KTOT);
        uint4* dst = (uint4*)smem;
        #pragma unroll
        for (int i = 0; i < 3; i++) {
            int lin = tid + i * NTHREADS;     // 0..1535
            int r = lin / 12, c = lin % 12;
            dst[r * 13 + c] = srcH[lin];
            dst[(IMG_BYTES / 16) + r * 13 + c] = srcL[lin];
        }
        if (tid < 128)
            ((float*)(smem + OFF_ASQ))[tid] = g_asq[rowBase + tid];
    };
    auto copyB = [&](int colTile, int stage) {
        const int colBase = colTile * 128;
        const char* srcH = (const char*)(g_Bh + (size_t)colBase * KTOT);
        const char* srcL = (const char*)(g_Bl + (size_t)colBase * KTOT);
        const uint32_t stBase = sb + OFF_STAGE0 + stage * STAGE_STRIDE;
        #pragma unroll
        for (int i = 0; i < 3; i++) {
            int lin = tid + i * NTHREADS;     // 0..1535
            int r = lin / 12, c = lin % 12;
            uint32_t doff = (uint32_t)(r * 13 + c) * 16;
            cp_async16(stBase + doff, srcH + lin * 16);
            cp_async16(stBase + IMG_BYTES + doff, srcL + lin * 16);
        }
        if (tid < 32)
            cp_async16(stBase + OFF_BSQ_ST + tid * 16,
                       (const char*)(g_bsq + colBase) + tid * 16);
    };

    const int wm = wid >> 2, wn = wid & 3;   // warp grid 4 x 4
    const int g = lane >> 2, t = lane & 3;
    const uint32_t aAddr = sb + OFF_A +
        (wm * 32 + (lane & 15)) * LDB + (lane >> 4) * 16;
    // B x4 over nj-pairs: lanes 0-7 rows 0-7 +0B, 8-15 rows 0-7 +16B,
    // 16-23 rows 8-15 +0B, 24-31 rows 8-15 +16B
    const uint32_t bLane = (wn * 32 + (lane & 7) + ((lane >> 4) << 3)) * LDB +
                           ((lane >> 3) & 1) * 16;
    const float* s_asq = (const float*)(smem + OFF_ASQ);

    int curRow = start / tilesC;
    loadA(curRow);
    copyB(start % tilesC, 0);
    CP_COMMIT();
    __syncthreads();

    for (int tt = start; tt < end; tt++) {
        const int stage = (tt - start) & 1;
        const int rt = tt / tilesC, ct = tt - rt * tilesC;
        const int rowBase = rt * 128, colBase = ct * 128;

        CP_WAIT0();
        __syncthreads();

        if (tt + 1 < end)
            copyB((tt + 1) % tilesC, stage ^ 1);
        CP_COMMIT();

        if (rt != curRow) {
            loadA(rt);
            curRow = rt;
            __syncthreads();
        }

        const uint32_t stBase = sb + OFF_STAGE0 + stage * STAGE_STRIDE;
        const uint32_t bAddr = stBase + bLane;
        const float* s_bsq = (const float*)(smem + OFF_STAGE0 +
                                            stage * STAGE_STRIDE + OFF_BSQ_ST);

        float acc[2][4][4];
        #pragma unroll
        for (int mi = 0; mi < 2; mi++)
            #pragma unroll
            for (int nj = 0; nj < 4; nj++)
                #pragma unroll
                for (int e = 0; e < 4; e++) acc[mi][nj][e] = 0.0f;

        // ---- raw k-steps 0..3 ----
        #pragma unroll
        for (int s = 0; s < 4; s++) {
            uint32_t ah[2][4], al[2][4], bh[2][4], bl[2][4];
            LOAD_FRAGS(s, ah, al, bh, bl);
            MMA_PAIR(0, ah, al, bh, bl);
            MMA_PAIR(1, ah, al, bh, bl);
        }

        // ---- transform constants ----
        float pka[2][2], pkb[8];
        #pragma unroll
        for (int mi = 0; mi < 2; mi++) {
            pka[mi][0] = fmaf(-NL2E, s_asq[wm * 32 + mi * 16 + g], -1.0f);
            pka[mi][1] = fmaf(-NL2E, s_asq[wm * 32 + mi * 16 + g + 8], -1.0f);
        }
        #pragma unroll
        for (int nj = 0; nj < 4; nj++) {
            pkb[2 * nj]     = -NL2E * s_bsq[wn * 32 + nj * 8 + 2 * t];
            pkb[2 * nj + 1] = -NL2E * s_bsq[wn * 32 + nj * 8 + 2 * t + 1];
        }

        // ---- feature k-step 4, interleaved with RBF transform ----
        {
            uint32_t ah[2][4], al[2][4], bh[2][4], bl[2][4];
            LOAD_FRAGS(4, ah, al, bh, bl);
            #pragma unroll
            for (int p = 0; p < 2; p++) {
                // transform the two nj of this pair
                #pragma unroll
                for (int nj = 2 * p; nj < 2 * p + 2; nj++)
                    #pragma unroll
                    for (int mi = 0; mi < 2; mi++) {
                        float* A = acc[mi][nj];
                        A[0] = ex2f(fminf(fmaf(A[0], TWO_L2E,
                                   pka[mi][0] + pkb[2 * nj]), -1.0f));
                        A[1] = ex2f(fminf(fmaf(A[1], TWO_L2E,
                                   pka[mi][0] + pkb[2 * nj + 1]), -1.0f));
                        A[2] = ex2f(fminf(fmaf(A[2], TWO_L2E,
                                   pka[mi][1] + pkb[2 * nj]), -1.0f));
                        A[3] = ex2f(fminf(fmaf(A[3], TWO_L2E,
                                   pka[mi][1] + pkb[2 * nj + 1]), -1.0f));
                    }
                MMA_PAIR(p, ah, al, bh, bl);
            }
            // ---- feature k-step 5 ----
            LOAD_FRAGS(5, ah, al, bh, bl);
            MMA_PAIR(0, ah, al, bh, bl);
            MMA_PAIR(1, ah, al, bh, bl);
        }

        // ---- store (streaming; output never re-read) ----
        #pragma unroll
        for (int mi = 0; mi < 2; mi++) {
            size_t r0 = (size_t)(rowBase + wm * 32 + mi * 16 + g);
            #pragma unroll
            for (int nj = 0; nj < 4; nj++) {
                int c = colBase + wn * 32 + nj * 8 + 2 * t;
                stg_cs_v2(out + r0 * M + c, acc[mi][nj][0], acc[mi][nj][1]);
                stg_cs_v2(out + (r0 + 8) * M + c, acc[mi][nj][2], acc[mi][nj][3]);
            }
        }
    }
}

// ---------------------------------------------------------------------------
extern "C" void kernel_launch(void* const* d_in, const int* in_sizes, int n_in,
                              void* d_out, int out_size)
{
    const float* a  = (const float*)d_in[0];
    const float* b  = (const float*)d_in[1];
    const float* W1 = (const float*)d_in[2];
    const float* b1 = (const float*)d_in[3];
    const float* W2 = (const float*)d_in[4];
    const float* b2 = (const float*)d_in[5];
    float* out = (float*)d_out;

    const int N = in_sizes[0] / DIM;   // 8192
    const int M = in_sizes[1] / DIM;   // 8192

    dim3 pgrid(N / 128, 2);
    prologue_kernel<<<pgrid, 128>>>(a, b, W1, b1, W2, b2);

    cudaFuncSetAttribute(gram_mma_kernel,
                         cudaFuncAttributeMaxDynamicSharedMemorySize, SMEM_DYN);
    gram_mma_kernel<<<GRID_CTAS, NTHREADS, SMEM_DYN>>>(out, M, N / 128, M / 128);
}